// round 1
// baseline (speedup 1.0000x reference)
#include <cuda_runtime.h>
#include <cstdint>

// Problem constants (fixed by the dataset)
constexpr int NN = 100000;   // nodes
constexpr int NE = 1600000;  // edges
constexpr int D  = 128;
constexpr int H  = 8;
// DH = 16, scale = 1/sqrt(16) = 0.25

// ---------------- scratch (static device globals; no runtime alloc) ----------
__device__ float g_Q [NN * D];
__device__ float g_K [NN * D];
__device__ float g_V [NN * D];
__device__ float g_wV[NN * D];
__device__ float g_a [NN * D];   // attention output, later reused as ff
__device__ float g_hh[NN * D];
__device__ float g_t [NN * 2 * D];
__device__ float g_z [NN * H];

// ---------------- zero init --------------------------------------------------
__global__ void zero_kernel(float* p, int n) {
    int i = blockIdx.x * blockDim.x + threadIdx.x;
    if (i < n) p[i] = 0.f;
}

// ---------------- tiled fp32 GEMM: C[M,N] = A[M,K] @ B[K,N] (+bias)(+relu) ---
// BM=64, BN=64, BK=16, TM=TN=4, 256 threads
template <bool RELU, bool BIAS>
__global__ void sgemm_kernel(const float* __restrict__ A,
                             const float* __restrict__ B,
                             const float* __restrict__ bias,
                             float* __restrict__ C,
                             int M, int N, int K) {
    constexpr int BM = 64, BN = 64, BK = 16, TM = 4, TN = 4;
    __shared__ float As[BK][BM + 4];
    __shared__ float Bs[BK][BN];

    const int tid = threadIdx.x;                // 0..255
    const int tx  = tid % (BN / TN);            // 0..15
    const int ty  = tid / (BN / TN);            // 0..15
    const int grow_base = blockIdx.y * BM;
    const int gcol_base = blockIdx.x * BN;

    float acc[TM][TN];
#pragma unroll
    for (int i = 0; i < TM; i++)
#pragma unroll
        for (int j = 0; j < TN; j++) acc[i][j] = 0.f;

    const int a_row  = tid / 4;         // 0..63
    const int a_col4 = (tid % 4) * 4;   // 0,4,8,12
    const int b_row  = tid / 16;        // 0..15
    const int b_col4 = (tid % 16) * 4;  // 0..60

    for (int k0 = 0; k0 < K; k0 += BK) {
        // load A tile (BM x BK), transpose into As
        float4 av = make_float4(0.f, 0.f, 0.f, 0.f);
        int gr = grow_base + a_row;
        if (gr < M)
            av = *reinterpret_cast<const float4*>(&A[(size_t)gr * K + k0 + a_col4]);
        As[a_col4 + 0][a_row] = av.x;
        As[a_col4 + 1][a_row] = av.y;
        As[a_col4 + 2][a_row] = av.z;
        As[a_col4 + 3][a_row] = av.w;
        // load B tile (BK x BN)
        float4 bv = *reinterpret_cast<const float4*>(
            &B[(size_t)(k0 + b_row) * N + gcol_base + b_col4]);
        *reinterpret_cast<float4*>(&Bs[b_row][b_col4]) = bv;
        __syncthreads();

#pragma unroll
        for (int k = 0; k < BK; k++) {
            float ar[TM], br[TN];
#pragma unroll
            for (int i = 0; i < TM; i++) ar[i] = As[k][ty * TM + i];
#pragma unroll
            for (int j = 0; j < TN; j++) br[j] = Bs[k][tx * TN + j];
#pragma unroll
            for (int i = 0; i < TM; i++)
#pragma unroll
                for (int j = 0; j < TN; j++) acc[i][j] += ar[i] * br[j];
        }
        __syncthreads();
    }

    // epilogue (vectorized float4 store per output row)
#pragma unroll
    for (int i = 0; i < TM; i++) {
        int gr = grow_base + ty * TM + i;
        if (gr >= M) continue;
        int gc = gcol_base + tx * TN;
        float4 v = make_float4(acc[i][0], acc[i][1], acc[i][2], acc[i][3]);
        if (BIAS) {
            float4 b4 = *reinterpret_cast<const float4*>(&bias[gc]);
            v.x += b4.x; v.y += b4.y; v.z += b4.z; v.w += b4.w;
        }
        if (RELU) {
            v.x = fmaxf(v.x, 0.f); v.y = fmaxf(v.y, 0.f);
            v.z = fmaxf(v.z, 0.f); v.w = fmaxf(v.w, 0.f);
        }
        *reinterpret_cast<float4*>(&C[(size_t)gr * N + gc]) = v;
    }
}

// ---------------- edge kernel: 1 warp per edge -------------------------------
// score[e,h] = exp(clip(dot(K[src,h,:],Q[dst,h,:]) * 0.25, -5, 5))
// wV[dst] += V[src]*score ; z[dst,h] += score
__global__ void edge_kernel(const int* __restrict__ src,
                            const int* __restrict__ dst,
                            const float* __restrict__ Q,
                            const float* __restrict__ K,
                            const float* __restrict__ V,
                            float* __restrict__ wV,
                            float* __restrict__ z) {
    int e = (blockIdx.x * blockDim.x + threadIdx.x) >> 5;
    if (e >= NE) return;
    int lane = threadIdx.x & 31;
    int s = src[e];
    int d = dst[e];

    float4 kv = reinterpret_cast<const float4*>(K + (size_t)s * D)[lane];
    float4 qv = reinterpret_cast<const float4*>(Q + (size_t)d * D)[lane];
    float p = kv.x * qv.x + kv.y * qv.y + kv.z * qv.z + kv.w * qv.w;
    // reduce within head group of 4 lanes (16 elems per head, 4 per lane)
    p += __shfl_xor_sync(0xffffffffu, p, 1);
    p += __shfl_xor_sync(0xffffffffu, p, 2);
    float sc = __expf(fminf(5.f, fmaxf(-5.f, p * 0.25f)));

    float4 vv = reinterpret_cast<const float4*>(V + (size_t)s * D)[lane];
    float* wp = wV + (size_t)d * D + lane * 4;
    atomicAdd(wp + 0, vv.x * sc);
    atomicAdd(wp + 1, vv.y * sc);
    atomicAdd(wp + 2, vv.z * sc);
    atomicAdd(wp + 3, vv.w * sc);
    if ((lane & 3) == 0) atomicAdd(&z[(size_t)d * H + (lane >> 2)], sc);
}

// ---------------- head_out = where(z>0, wV/z, wV) (in place on wV) -----------
__global__ void divz_kernel(float* __restrict__ wV, const float* __restrict__ z) {
    int i4 = blockIdx.x * blockDim.x + threadIdx.x;  // float4 index
    if (i4 >= NN * D / 4) return;
    int idx = i4 * 4;
    int n = idx >> 7;                 // /128
    int h = (idx >> 4) & 7;           // 16 elems per head
    float zz = z[(size_t)n * H + h];
    float4 w = reinterpret_cast<float4*>(wV)[i4];
    if (zz > 0.f) {
        float inv = 1.f / zz;
        w.x *= inv; w.y *= inv; w.z *= inv; w.w *= inv;
    }
    reinterpret_cast<float4*>(wV)[i4] = w;
}

// ---------------- layernorm: out = LN(x + y) * g + b, row width 128 ----------
__global__ void ln_kernel(const float* __restrict__ x,
                          const float* __restrict__ y,
                          const float* __restrict__ g,
                          const float* __restrict__ b,
                          float* __restrict__ out, int nrows) {
    int row  = (blockIdx.x * blockDim.x + threadIdx.x) >> 5;
    int lane = threadIdx.x & 31;
    if (row >= nrows) return;
    float4 xv = reinterpret_cast<const float4*>(x + (size_t)row * D)[lane];
    float4 yv = reinterpret_cast<const float4*>(y + (size_t)row * D)[lane];
    float v0 = xv.x + yv.x, v1 = xv.y + yv.y, v2 = xv.z + yv.z, v3 = xv.w + yv.w;
    float s  = v0 + v1 + v2 + v3;
    float s2 = v0 * v0 + v1 * v1 + v2 * v2 + v3 * v3;
#pragma unroll
    for (int o = 16; o > 0; o >>= 1) {
        s  += __shfl_xor_sync(0xffffffffu, s,  o);
        s2 += __shfl_xor_sync(0xffffffffu, s2, o);
    }
    float mu   = s * (1.f / 128.f);
    float var  = s2 * (1.f / 128.f) - mu * mu;
    float rstd = rsqrtf(var + 1e-5f);
    float4 gv = reinterpret_cast<const float4*>(g)[lane];
    float4 bv = reinterpret_cast<const float4*>(b)[lane];
    float4 o4;
    o4.x = (v0 - mu) * rstd * gv.x + bv.x;
    o4.y = (v1 - mu) * rstd * gv.y + bv.y;
    o4.z = (v2 - mu) * rstd * gv.z + bv.z;
    o4.w = (v3 - mu) * rstd * gv.w + bv.w;
    reinterpret_cast<float4*>(out + (size_t)row * D)[lane] = o4;
}

// ---------------- launch -----------------------------------------------------
extern "C" void kernel_launch(void* const* d_in, const int* in_sizes, int n_in,
                              void* d_out, int out_size) {
    const float* h   = (const float*)d_in[0];
    const int*   src = (const int*)  d_in[1];
    const int*   dst = (const int*)  d_in[2];
    const float* Wq  = (const float*)d_in[3];
    const float* Wk  = (const float*)d_in[4];
    const float* Wv  = (const float*)d_in[5];
    const float* Wo  = (const float*)d_in[6];
    const float* bo  = (const float*)d_in[7];
    const float* g1  = (const float*)d_in[8];
    const float* b1  = (const float*)d_in[9];
    const float* g2  = (const float*)d_in[10];
    const float* b2  = (const float*)d_in[11];
    const float* W1  = (const float*)d_in[12];
    const float* c1  = (const float*)d_in[13];
    const float* W2  = (const float*)d_in[14];
    const float* c2  = (const float*)d_in[15];
    float* out = (float*)d_out;

    float *Qp, *Kp, *Vp, *wVp, *ap, *hhp, *tp, *zp;
    cudaGetSymbolAddress((void**)&Qp,  g_Q);
    cudaGetSymbolAddress((void**)&Kp,  g_K);
    cudaGetSymbolAddress((void**)&Vp,  g_V);
    cudaGetSymbolAddress((void**)&wVp, g_wV);
    cudaGetSymbolAddress((void**)&ap,  g_a);
    cudaGetSymbolAddress((void**)&hhp, g_hh);
    cudaGetSymbolAddress((void**)&tp,  g_t);
    cudaGetSymbolAddress((void**)&zp,  g_z);

    // zero wV and z
    {
        int n = NN * D;
        zero_kernel<<<(n + 255) / 256, 256>>>(wVp, n);
        int n2 = NN * H;
        zero_kernel<<<(n2 + 255) / 256, 256>>>(zp, n2);
    }

    // QKV projections
    {
        dim3 grid(D / 64, (NN + 63) / 64);
        sgemm_kernel<false, false><<<grid, 256>>>(h, Wq, nullptr, Qp, NN, D, D);
        sgemm_kernel<false, false><<<grid, 256>>>(h, Wk, nullptr, Kp, NN, D, D);
        sgemm_kernel<false, false><<<grid, 256>>>(h, Wv, nullptr, Vp, NN, D, D);
    }

    // edge attention (1 warp / edge)
    {
        long long threads = (long long)NE * 32;
        int blocks = (int)((threads + 255) / 256);
        edge_kernel<<<blocks, 256>>>(src, dst, Qp, Kp, Vp, wVp, zp);
    }

    // head_out = wV / z (guarded)
    {
        int n4 = NN * D / 4;
        divz_kernel<<<(n4 + 255) / 256, 256>>>(wVp, zp);
    }

    // a = head_out @ Wo + bo
    {
        dim3 grid(D / 64, (NN + 63) / 64);
        sgemm_kernel<false, true><<<grid, 256>>>(wVp, Wo, bo, ap, NN, D, D);
    }

    // hh = LN(h + a)
    {
        int threads = 256;
        int blocks = (NN * 32 + threads - 1) / threads;
        ln_kernel<<<blocks, threads>>>(h, ap, g1, b1, hhp, NN);
    }

    // t = relu(hh @ W1 + c1)   [100k x 256]
    {
        dim3 grid((2 * D) / 64, (NN + 63) / 64);
        sgemm_kernel<true, true><<<grid, 256>>>(hhp, W1, c1, tp, NN, 2 * D, D);
    }

    // ff = t @ W2 + c2  (reuse g_a)
    {
        dim3 grid(D / 64, (NN + 63) / 64);
        sgemm_kernel<false, true><<<grid, 256>>>(tp, W2, c2, ap, NN, D, 2 * D);
    }

    // out = LN(hh + ff)
    {
        int threads = 256;
        int blocks = (NN * 32 + threads - 1) / threads;
        ln_kernel<<<blocks, threads>>>(hhp, ap, g2, b2, out, NN);
    }
}

// round 2
// speedup vs baseline: 1.2484x; 1.2484x over previous
#include <cuda_runtime.h>
#include <cstdint>

constexpr int NN = 100000;   // nodes
constexpr int NE = 1600000;  // edges
constexpr int D  = 128;
constexpr int H  = 8;
// DH = 16, scale = 0.25

// ---------------- scratch ----------------------------------------------------
__device__ float g_QKV[NN * 3 * D];  // packed per node: [Q(128) | K(128) | V(128)]
__device__ float g_Wpk[D * 3 * D];   // packed weights [k][Wq|Wk|Wv]
__device__ float g_wV [NN * D];
__device__ float g_a  [NN * D];      // attn out, later ff out
__device__ float g_hh [NN * D];
__device__ float g_t  [NN * 2 * D];
__device__ float g_z  [NN * H];

// ---------------- pack Wq|Wk|Wv into [128 x 384] -----------------------------
__global__ void packW_kernel(const float* __restrict__ Wq,
                             const float* __restrict__ Wk,
                             const float* __restrict__ Wv,
                             float* __restrict__ P) {
    int i = blockIdx.x * blockDim.x + threadIdx.x;   // 0 .. 128*128-1
    if (i >= D * D) return;
    int k = i / D, c = i % D;
    P[(size_t)k * (3 * D) + c]         = Wq[i];
    P[(size_t)k * (3 * D) + D + c]     = Wk[i];
    P[(size_t)k * (3 * D) + 2 * D + c] = Wv[i];
}

// ---------------- big-tile fp32 GEMM: C[M,N] = A[M,K] @ B[K,N] ---------------
// BM=128, BN=128, BK=16, TM=TN=8, 256 threads
template <bool RELU, bool BIAS>
__global__ void __launch_bounds__(256, 2)
sgemm128(const float* __restrict__ A, const float* __restrict__ B,
         const float* __restrict__ bias, float* __restrict__ C,
         int M, int N, int K) {
    constexpr int BM = 128, BN = 128, BK = 16;
    __shared__ float As[BK][BM + 4];
    __shared__ float Bs[BK][BN];

    const int tid  = threadIdx.x;
    const int tx   = tid % 16;
    const int ty   = tid / 16;
    const int row0 = blockIdx.y * BM;
    const int col0 = blockIdx.x * BN;

    float acc[8][8];
#pragma unroll
    for (int i = 0; i < 8; i++)
#pragma unroll
        for (int j = 0; j < 8; j++) acc[i][j] = 0.f;

    const int ar = tid / 4;            // 0..63 (A rows, 2 batches of 64)
    const int ac = (tid % 4) * 4;      // 0..12
    const int br = tid / 32;           // 0..7  (B rows, 2 batches of 8)
    const int bc = (tid % 32) * 4;     // 0..124

    for (int k0 = 0; k0 < K; k0 += BK) {
#pragma unroll
        for (int i = 0; i < 2; i++) {
            int r = row0 + ar + i * 64;
            float4 v = make_float4(0.f, 0.f, 0.f, 0.f);
            if (r < M)
                v = *reinterpret_cast<const float4*>(&A[(size_t)r * K + k0 + ac]);
            As[ac + 0][ar + i * 64] = v.x;
            As[ac + 1][ar + i * 64] = v.y;
            As[ac + 2][ar + i * 64] = v.z;
            As[ac + 3][ar + i * 64] = v.w;
        }
#pragma unroll
        for (int i = 0; i < 2; i++) {
            int r = k0 + br + i * 8;
            float4 v = *reinterpret_cast<const float4*>(&B[(size_t)r * N + col0 + bc]);
            *reinterpret_cast<float4*>(&Bs[br + i * 8][bc]) = v;
        }
        __syncthreads();

#pragma unroll
        for (int k = 0; k < BK; k++) {
            float a[8], b[8];
            *reinterpret_cast<float4*>(&a[0]) =
                *reinterpret_cast<float4*>(&As[k][ty * 8]);
            *reinterpret_cast<float4*>(&a[4]) =
                *reinterpret_cast<float4*>(&As[k][ty * 8 + 4]);
            *reinterpret_cast<float4*>(&b[0]) =
                *reinterpret_cast<float4*>(&Bs[k][tx * 8]);
            *reinterpret_cast<float4*>(&b[4]) =
                *reinterpret_cast<float4*>(&Bs[k][tx * 8 + 4]);
#pragma unroll
            for (int i = 0; i < 8; i++)
#pragma unroll
                for (int j = 0; j < 8; j++) acc[i][j] += a[i] * b[j];
        }
        __syncthreads();
    }

#pragma unroll
    for (int i = 0; i < 8; i++) {
        int r = row0 + ty * 8 + i;
        if (r >= M) continue;
        int c = col0 + tx * 8;
#pragma unroll
        for (int jj = 0; jj < 2; jj++) {
            float4 v = make_float4(acc[i][jj * 4 + 0], acc[i][jj * 4 + 1],
                                   acc[i][jj * 4 + 2], acc[i][jj * 4 + 3]);
            if (BIAS) {
                float4 b4 = *reinterpret_cast<const float4*>(&bias[c + jj * 4]);
                v.x += b4.x; v.y += b4.y; v.z += b4.z; v.w += b4.w;
            }
            if (RELU) {
                v.x = fmaxf(v.x, 0.f); v.y = fmaxf(v.y, 0.f);
                v.z = fmaxf(v.z, 0.f); v.w = fmaxf(v.w, 0.f);
            }
            *reinterpret_cast<float4*>(&C[(size_t)r * N + c + jj * 4]) = v;
        }
    }
}

// ---------------- edge kernel: 1 warp / edge, packed QKV, v4 atomics ---------
__global__ void edge_kernel(const int* __restrict__ src,
                            const int* __restrict__ dst,
                            const float* __restrict__ QKV,
                            float* __restrict__ wV,
                            float* __restrict__ z) {
    int e = (blockIdx.x * blockDim.x + threadIdx.x) >> 5;
    if (e >= NE) return;
    int lane = threadIdx.x & 31;
    int s = src[e];
    int d = dst[e];

    const float* srow = QKV + (size_t)s * (3 * D);   // K at +128, V at +256
    const float* drow = QKV + (size_t)d * (3 * D);   // Q at +0

    float4 kv = reinterpret_cast<const float4*>(srow + D)[lane];
    float4 qv = reinterpret_cast<const float4*>(drow)[lane];
    float p = kv.x * qv.x + kv.y * qv.y + kv.z * qv.z + kv.w * qv.w;
    p += __shfl_xor_sync(0xffffffffu, p, 1);
    p += __shfl_xor_sync(0xffffffffu, p, 2);
    float sc = __expf(fminf(5.f, fmaxf(-5.f, p * 0.25f)));

    float4 vv = reinterpret_cast<const float4*>(srow + 2 * D)[lane];
    float* wp = wV + (size_t)d * D + lane * 4;
    asm volatile("red.global.add.v4.f32 [%0], {%1, %2, %3, %4};"
                 :: "l"(wp), "f"(vv.x * sc), "f"(vv.y * sc),
                    "f"(vv.z * sc), "f"(vv.w * sc)
                 : "memory");
    if ((lane & 3) == 0) atomicAdd(&z[(size_t)d * H + (lane >> 2)], sc);
}

// ---------------- head_out = where(z>0, wV/z, wV) (in place) -----------------
__global__ void divz_kernel(float* __restrict__ wV, const float* __restrict__ z) {
    int i4 = blockIdx.x * blockDim.x + threadIdx.x;
    if (i4 >= NN * D / 4) return;
    int idx = i4 * 4;
    int n = idx >> 7;
    int h = (idx >> 4) & 7;
    float zz = z[(size_t)n * H + h];
    float4 w = reinterpret_cast<float4*>(wV)[i4];
    if (zz > 0.f) {
        float inv = 1.f / zz;
        w.x *= inv; w.y *= inv; w.z *= inv; w.w *= inv;
    }
    reinterpret_cast<float4*>(wV)[i4] = w;
}

// ---------------- layernorm: out = LN(x + y) * g + b -------------------------
__global__ void ln_kernel(const float* __restrict__ x,
                          const float* __restrict__ y,
                          const float* __restrict__ g,
                          const float* __restrict__ b,
                          float* __restrict__ out, int nrows) {
    int row  = (blockIdx.x * blockDim.x + threadIdx.x) >> 5;
    int lane = threadIdx.x & 31;
    if (row >= nrows) return;
    float4 xv = reinterpret_cast<const float4*>(x + (size_t)row * D)[lane];
    float4 yv = reinterpret_cast<const float4*>(y + (size_t)row * D)[lane];
    float v0 = xv.x + yv.x, v1 = xv.y + yv.y, v2 = xv.z + yv.z, v3 = xv.w + yv.w;
    float s  = v0 + v1 + v2 + v3;
    float s2 = v0 * v0 + v1 * v1 + v2 * v2 + v3 * v3;
#pragma unroll
    for (int o = 16; o > 0; o >>= 1) {
        s  += __shfl_xor_sync(0xffffffffu, s,  o);
        s2 += __shfl_xor_sync(0xffffffffu, s2, o);
    }
    float mu   = s * (1.f / 128.f);
    float var  = s2 * (1.f / 128.f) - mu * mu;
    float rstd = rsqrtf(var + 1e-5f);
    float4 gv = reinterpret_cast<const float4*>(g)[lane];
    float4 bv = reinterpret_cast<const float4*>(b)[lane];
    float4 o4;
    o4.x = (v0 - mu) * rstd * gv.x + bv.x;
    o4.y = (v1 - mu) * rstd * gv.y + bv.y;
    o4.z = (v2 - mu) * rstd * gv.z + bv.z;
    o4.w = (v3 - mu) * rstd * gv.w + bv.w;
    reinterpret_cast<float4*>(out + (size_t)row * D)[lane] = o4;
}

// ---------------- launch -----------------------------------------------------
extern "C" void kernel_launch(void* const* d_in, const int* in_sizes, int n_in,
                              void* d_out, int out_size) {
    const float* h   = (const float*)d_in[0];
    const int*   src = (const int*)  d_in[1];
    const int*   dst = (const int*)  d_in[2];
    const float* Wq  = (const float*)d_in[3];
    const float* Wk  = (const float*)d_in[4];
    const float* Wv  = (const float*)d_in[5];
    const float* Wo  = (const float*)d_in[6];
    const float* bo  = (const float*)d_in[7];
    const float* g1  = (const float*)d_in[8];
    const float* b1  = (const float*)d_in[9];
    const float* g2  = (const float*)d_in[10];
    const float* b2  = (const float*)d_in[11];
    const float* W1  = (const float*)d_in[12];
    const float* c1  = (const float*)d_in[13];
    const float* W2  = (const float*)d_in[14];
    const float* c2  = (const float*)d_in[15];
    float* out = (float*)d_out;

    float *QKVp, *Wpkp, *wVp, *ap, *hhp, *tp, *zp;
    cudaGetSymbolAddress((void**)&QKVp, g_QKV);
    cudaGetSymbolAddress((void**)&Wpkp, g_Wpk);
    cudaGetSymbolAddress((void**)&wVp,  g_wV);
    cudaGetSymbolAddress((void**)&ap,   g_a);
    cudaGetSymbolAddress((void**)&hhp,  g_hh);
    cudaGetSymbolAddress((void**)&tp,   g_t);
    cudaGetSymbolAddress((void**)&zp,   g_z);

    // zero accumulators (graph-capturable)
    cudaMemsetAsync(wVp, 0, (size_t)NN * D * sizeof(float));
    cudaMemsetAsync(zp,  0, (size_t)NN * H * sizeof(float));

    // pack weights and run fused QKV GEMM: [100000 x 128] @ [128 x 384]
    packW_kernel<<<(D * D + 255) / 256, 256>>>(Wq, Wk, Wv, Wpkp);
    {
        dim3 grid(3, (NN + 127) / 128);
        sgemm128<false, false><<<grid, 256>>>(h, Wpkp, nullptr, QKVp, NN, 3 * D, D);
    }

    // edge attention
    {
        long long threads = (long long)NE * 32;
        int blocks = (int)((threads + 255) / 256);
        edge_kernel<<<blocks, 256>>>(src, dst, QKVp, wVp, zp);
    }

    // head_out = wV / z
    {
        int n4 = NN * D / 4;
        divz_kernel<<<(n4 + 255) / 256, 256>>>(wVp, zp);
    }

    // a = head_out @ Wo + bo
    {
        dim3 grid(1, (NN + 127) / 128);
        sgemm128<false, true><<<grid, 256>>>(wVp, Wo, bo, ap, NN, D, D);
    }

    // hh = LN(h + a)
    {
        int blocks = (NN * 32 + 255) / 256;
        ln_kernel<<<blocks, 256>>>(h, ap, g1, b1, hhp, NN);
    }

    // t = relu(hh @ W1 + c1)
    {
        dim3 grid(2, (NN + 127) / 128);
        sgemm128<true, true><<<grid, 256>>>(hhp, W1, c1, tp, NN, 2 * D, D);
    }

    // ff = t @ W2 + c2 (reuse g_a)
    {
        dim3 grid(1, (NN + 127) / 128);
        sgemm128<false, true><<<grid, 256>>>(tp, W2, c2, ap, NN, D, 2 * D);
    }

    // out = LN(hh + ff)
    {
        int blocks = (NN * 32 + 255) / 256;
        ln_kernel<<<blocks, 256>>>(hhp, ap, g2, b2, out, NN);
    }
}

// round 4
// speedup vs baseline: 1.3853x; 1.1097x over previous
#include <cuda_runtime.h>
#include <cstdint>

constexpr int NN = 100000;   // nodes
constexpr int NE = 1600000;  // edges
constexpr int D  = 128;
constexpr int H  = 8;
// DH = 16, scale = 0.25

// ---------------- scratch ----------------------------------------------------
__device__ float g_QKV[NN * 3 * D];  // packed per node: [Q(128) | K(128) | V(128)]
__device__ float g_Wpk[D * 3 * D];   // packed weights [k][Wq|Wk|Wv]
__device__ float g_wV [NN * D];      // head_out
__device__ float g_a  [NN * D];      // attn out, later ff out
__device__ float g_hh [NN * D];
__device__ float g_t  [NN * 2 * D];
__device__ int   g_cnt[NN];
__device__ int   g_off[NN + 1];
__device__ int   g_cur[NN];
__device__ int   g_bin[NE];          // src ids binned by dst

// ---------------- pack Wq|Wk|Wv into [128 x 384] -----------------------------
__global__ void __launch_bounds__(256)
packW_kernel(const float* __restrict__ Wq,
             const float* __restrict__ Wk,
             const float* __restrict__ Wv,
             float* __restrict__ P) {
    int i = blockIdx.x * blockDim.x + threadIdx.x;
    if (i >= D * D) return;
    int k = i / D, c = i % D;
    P[(size_t)k * (3 * D) + c]         = Wq[i];
    P[(size_t)k * (3 * D) + D + c]     = Wk[i];
    P[(size_t)k * (3 * D) + 2 * D + c] = Wv[i];
}

// ---------------- big-tile fp32 GEMM: C[M,N] = A[M,K] @ B[K,N] ---------------
template <bool RELU, bool BIAS>
__global__ void __launch_bounds__(256, 2)
sgemm128(const float* __restrict__ A, const float* __restrict__ B,
         const float* __restrict__ bias, float* __restrict__ C,
         int M, int N, int K) {
    constexpr int BK = 16;
    __shared__ float As[BK][128 + 4];
    __shared__ float Bs[BK][128];

    const int tid  = threadIdx.x;
    const int tx   = tid % 16;
    const int ty   = tid / 16;
    const int row0 = blockIdx.y * 128;
    const int col0 = blockIdx.x * 128;

    float acc[8][8];
#pragma unroll
    for (int i = 0; i < 8; i++)
#pragma unroll
        for (int j = 0; j < 8; j++) acc[i][j] = 0.f;

    const int ar = tid / 4;
    const int ac = (tid % 4) * 4;
    const int br = tid / 32;
    const int bc = (tid % 32) * 4;

    for (int k0 = 0; k0 < K; k0 += BK) {
#pragma unroll
        for (int i = 0; i < 2; i++) {
            int r = row0 + ar + i * 64;
            float4 v = make_float4(0.f, 0.f, 0.f, 0.f);
            if (r < M)
                v = *reinterpret_cast<const float4*>(&A[(size_t)r * K + k0 + ac]);
            As[ac + 0][ar + i * 64] = v.x;
            As[ac + 1][ar + i * 64] = v.y;
            As[ac + 2][ar + i * 64] = v.z;
            As[ac + 3][ar + i * 64] = v.w;
        }
#pragma unroll
        for (int i = 0; i < 2; i++) {
            int r = k0 + br + i * 8;
            float4 v = *reinterpret_cast<const float4*>(&B[(size_t)r * N + col0 + bc]);
            *reinterpret_cast<float4*>(&Bs[br + i * 8][bc]) = v;
        }
        __syncthreads();

#pragma unroll
        for (int k = 0; k < BK; k++) {
            float a[8], b[8];
            *reinterpret_cast<float4*>(&a[0]) = *reinterpret_cast<float4*>(&As[k][ty * 8]);
            *reinterpret_cast<float4*>(&a[4]) = *reinterpret_cast<float4*>(&As[k][ty * 8 + 4]);
            *reinterpret_cast<float4*>(&b[0]) = *reinterpret_cast<float4*>(&Bs[k][tx * 8]);
            *reinterpret_cast<float4*>(&b[4]) = *reinterpret_cast<float4*>(&Bs[k][tx * 8 + 4]);
#pragma unroll
            for (int i = 0; i < 8; i++)
#pragma unroll
                for (int j = 0; j < 8; j++) acc[i][j] += a[i] * b[j];
        }
        __syncthreads();
    }

#pragma unroll
    for (int i = 0; i < 8; i++) {
        int r = row0 + ty * 8 + i;
        if (r >= M) continue;
        int c = col0 + tx * 8;
#pragma unroll
        for (int jj = 0; jj < 2; jj++) {
            float4 v = make_float4(acc[i][jj * 4 + 0], acc[i][jj * 4 + 1],
                                   acc[i][jj * 4 + 2], acc[i][jj * 4 + 3]);
            if (BIAS) {
                float4 b4 = *reinterpret_cast<const float4*>(&bias[c + jj * 4]);
                v.x += b4.x; v.y += b4.y; v.z += b4.z; v.w += b4.w;
            }
            if (RELU) {
                v.x = fmaxf(v.x, 0.f); v.y = fmaxf(v.y, 0.f);
                v.z = fmaxf(v.z, 0.f); v.w = fmaxf(v.w, 0.f);
            }
            *reinterpret_cast<float4*>(&C[(size_t)r * N + c + jj * 4]) = v;
        }
    }
}

// ---------------- binning: count / scan / scatter -----------------------------
__global__ void __launch_bounds__(256)
count_kernel(const int* __restrict__ dst, int* __restrict__ cnt) {
    int e = blockIdx.x * blockDim.x + threadIdx.x;
    if (e < NE) atomicAdd(&cnt[dst[e]], 1);
}

// single-block exclusive scan over cnt[NN] -> off[NN+1]
__global__ void __launch_bounds__(1024)
scan_kernel(const int* __restrict__ cnt, int* __restrict__ off) {
    __shared__ int s[1024];
    const int t  = threadIdx.x;
    const int CH = (NN + 1023) / 1024;  // 98
    const int base = t * CH;
    int sum = 0;
    for (int i = 0; i < CH; i++) {
        int idx = base + i;
        if (idx < NN) sum += cnt[idx];
    }
    s[t] = sum;
    __syncthreads();
    // Hillis-Steele inclusive scan
    for (int o = 1; o < 1024; o <<= 1) {
        int v = (t >= o) ? s[t - o] : 0;
        __syncthreads();
        s[t] += v;
        __syncthreads();
    }
    int run = (t == 0) ? 0 : s[t - 1];  // exclusive prefix
    for (int i = 0; i < CH; i++) {
        int idx = base + i;
        if (idx < NN) { off[idx] = run; run += cnt[idx]; }
    }
    if (t == 1023) off[NN] = run;
}

__global__ void __launch_bounds__(256)
scatter_kernel(const int* __restrict__ src,
               const int* __restrict__ dst,
               const int* __restrict__ off,
               int* __restrict__ cur,
               int* __restrict__ bin) {
    int e = blockIdx.x * blockDim.x + threadIdx.x;
    if (e >= NE) return;
    int d = dst[e];
    int pos = atomicAdd(&cur[d], 1);
    bin[off[d] + pos] = src[e];
}

// ---------------- aggregation: 1 warp per dst node, no atomics ----------------
// head_out[n] = (sum_e V[src]*sc) / z  with z>0 guard fused
__global__ void __launch_bounds__(256)
agg_kernel(const int* __restrict__ off,
           const int* __restrict__ bin,
           const float* __restrict__ QKV,
           float* __restrict__ head_out) {
    int n = (blockIdx.x * blockDim.x + threadIdx.x) >> 5;
    if (n >= NN) return;
    int lane = threadIdx.x & 31;
    int beg = off[n], end = off[n + 1];

    float4 q = reinterpret_cast<const float4*>(QKV + (size_t)n * (3 * D))[lane];
    float4 acc = make_float4(0.f, 0.f, 0.f, 0.f);
    float zt = 0.f;

    int s = (beg < end) ? bin[beg] : 0;
    for (int i = beg; i < end; i++) {
        int snext = (i + 1 < end) ? bin[i + 1] : 0;
        const float* sr = QKV + (size_t)s * (3 * D);
        float4 kv = reinterpret_cast<const float4*>(sr + D)[lane];
        float4 vv = reinterpret_cast<const float4*>(sr + 2 * D)[lane];
        float p = kv.x * q.x + kv.y * q.y + kv.z * q.z + kv.w * q.w;
        p += __shfl_xor_sync(0xffffffffu, p, 1);
        p += __shfl_xor_sync(0xffffffffu, p, 2);
        float sc = __expf(fminf(5.f, fmaxf(-5.f, p * 0.25f)));
        acc.x += vv.x * sc;
        acc.y += vv.y * sc;
        acc.z += vv.z * sc;
        acc.w += vv.w * sc;
        zt += sc;
        s = snext;
    }
    if (zt > 0.f) {
        float inv = 1.f / zt;
        acc.x *= inv; acc.y *= inv; acc.z *= inv; acc.w *= inv;
    }
    reinterpret_cast<float4*>(head_out + (size_t)n * D)[lane] = acc;
}

// ---------------- layernorm: out = LN(x + y) * g + b -------------------------
__global__ void __launch_bounds__(256)
ln_kernel(const float* __restrict__ x,
          const float* __restrict__ y,
          const float* __restrict__ g,
          const float* __restrict__ b,
          float* __restrict__ out, int nrows) {
    int row  = (blockIdx.x * blockDim.x + threadIdx.x) >> 5;
    int lane = threadIdx.x & 31;
    if (row >= nrows) return;
    float4 xv = reinterpret_cast<const float4*>(x + (size_t)row * D)[lane];
    float4 yv = reinterpret_cast<const float4*>(y + (size_t)row * D)[lane];
    float v0 = xv.x + yv.x, v1 = xv.y + yv.y, v2 = xv.z + yv.z, v3 = xv.w + yv.w;
    float s  = v0 + v1 + v2 + v3;
    float s2 = v0 * v0 + v1 * v1 + v2 * v2 + v3 * v3;
#pragma unroll
    for (int o = 16; o > 0; o >>= 1) {
        s  += __shfl_xor_sync(0xffffffffu, s,  o);
        s2 += __shfl_xor_sync(0xffffffffu, s2, o);
    }
    float mu   = s * (1.f / 128.f);
    float var  = s2 * (1.f / 128.f) - mu * mu;
    float rstd = rsqrtf(var + 1e-5f);
    float4 gv = reinterpret_cast<const float4*>(g)[lane];
    float4 bv = reinterpret_cast<const float4*>(b)[lane];
    float4 o4;
    o4.x = (v0 - mu) * rstd * gv.x + bv.x;
    o4.y = (v1 - mu) * rstd * gv.y + bv.y;
    o4.z = (v2 - mu) * rstd * gv.z + bv.z;
    o4.w = (v3 - mu) * rstd * gv.w + bv.w;
    reinterpret_cast<float4*>(out + (size_t)row * D)[lane] = o4;
}

// ---------------- launch -----------------------------------------------------
extern "C" void kernel_launch(void* const* d_in, const int* in_sizes, int n_in,
                              void* d_out, int out_size) {
    const float* h   = (const float*)d_in[0];
    const int*   src = (const int*)  d_in[1];
    const int*   dst = (const int*)  d_in[2];
    const float* Wq  = (const float*)d_in[3];
    const float* Wk  = (const float*)d_in[4];
    const float* Wv  = (const float*)d_in[5];
    const float* Wo  = (const float*)d_in[6];
    const float* bo  = (const float*)d_in[7];
    const float* g1  = (const float*)d_in[8];
    const float* b1  = (const float*)d_in[9];
    const float* g2  = (const float*)d_in[10];
    const float* b2  = (const float*)d_in[11];
    const float* W1  = (const float*)d_in[12];
    const float* c1  = (const float*)d_in[13];
    const float* W2  = (const float*)d_in[14];
    const float* c2  = (const float*)d_in[15];
    float* out = (float*)d_out;

    float *QKVp, *Wpkp, *wVp, *ap, *hhp, *tp;
    int *cntp, *offp, *curp, *binp;
    cudaGetSymbolAddress((void**)&QKVp, g_QKV);
    cudaGetSymbolAddress((void**)&Wpkp, g_Wpk);
    cudaGetSymbolAddress((void**)&wVp,  g_wV);
    cudaGetSymbolAddress((void**)&ap,   g_a);
    cudaGetSymbolAddress((void**)&hhp,  g_hh);
    cudaGetSymbolAddress((void**)&tp,   g_t);
    cudaGetSymbolAddress((void**)&cntp, g_cnt);
    cudaGetSymbolAddress((void**)&offp, g_off);
    cudaGetSymbolAddress((void**)&curp, g_cur);
    cudaGetSymbolAddress((void**)&binp, g_bin);

    // --- binning by dst ---
    cudaMemsetAsync(cntp, 0, NN * sizeof(int));
    cudaMemsetAsync(curp, 0, NN * sizeof(int));
    count_kernel<<<(NE + 255) / 256, 256>>>(dst, cntp);
    scan_kernel<<<1, 1024>>>(cntp, offp);
    scatter_kernel<<<(NE + 255) / 256, 256>>>(src, dst, offp, curp, binp);

    // --- fused QKV GEMM: [100000 x 128] @ [128 x 384] ---
    packW_kernel<<<(D * D + 255) / 256, 256>>>(Wq, Wk, Wv, Wpkp);
    {
        dim3 grid(3, (NN + 127) / 128);
        sgemm128<false, false><<<grid, 256>>>(h, Wpkp, nullptr, QKVp, NN, 3 * D, D);
    }

    // --- attention aggregation (atomic-free, division fused) ---
    {
        int blocks = (NN * 32 + 255) / 256;
        agg_kernel<<<blocks, 256>>>(offp, binp, QKVp, wVp);
    }

    // a = head_out @ Wo + bo
    {
        dim3 grid(1, (NN + 127) / 128);
        sgemm128<false, true><<<grid, 256>>>(wVp, Wo, bo, ap, NN, D, D);
    }

    // hh = LN(h + a)
    {
        int blocks = (NN * 32 + 255) / 256;
        ln_kernel<<<blocks, 256>>>(h, ap, g1, b1, hhp, NN);
    }

    // t = relu(hh @ W1 + c1)
    {
        dim3 grid(2, (NN + 127) / 128);
        sgemm128<true, true><<<grid, 256>>>(hhp, W1, c1, tp, NN, 2 * D, D);
    }

    // ff = t @ W2 + c2 (reuse g_a)
    {
        dim3 grid(1, (NN + 127) / 128);
        sgemm128<false, true><<<grid, 256>>>(tp, W2, c2, ap, NN, D, 2 * D);
    }

    // out = LN(hh + ff)
    {
        int blocks = (NN * 32 + 255) / 256;
        ln_kernel<<<blocks, 256>>>(hhp, ap, g2, b2, out, NN);
    }
}

// round 5
// speedup vs baseline: 1.4479x; 1.0453x over previous
#include <cuda_runtime.h>
#include <cstdint>

constexpr int NN = 100000;   // nodes
constexpr int NE = 1600000;  // edges
constexpr int D  = 128;
// H=8, DH=16, scale=0.25

// ---------------- scratch ----------------------------------------------------
__device__ float g_Q  [NN * D];        // Q rows (streamed in agg)
__device__ float g_KV [NN * 2 * D];    // per node: [K(128) | V(128)] (gathered)
__device__ float g_Wpk[D * 3 * D];     // packed weights [k][Wq|Wk|Wv]
__device__ float g_wV [NN * D];        // head_out
__device__ float g_hh [NN * D];
__device__ float g_t  [NN * 2 * D];
__device__ int   g_cnt[NN];
__device__ int   g_off[NN + 1];
__device__ int   g_cur[NN];
__device__ int   g_bin[NE];            // src ids binned by dst

// ---------------- pack Wq|Wk|Wv into [128 x 384] -----------------------------
__global__ void __launch_bounds__(256)
packW_kernel(const float* __restrict__ Wq,
             const float* __restrict__ Wk,
             const float* __restrict__ Wv,
             float* __restrict__ P) {
    int i = blockIdx.x * blockDim.x + threadIdx.x;
    if (i >= D * D) return;
    int k = i / D, c = i % D;
    P[(size_t)k * (3 * D) + c]         = Wq[i];
    P[(size_t)k * (3 * D) + D + c]     = Wk[i];
    P[(size_t)k * (3 * D) + 2 * D + c] = Wv[i];
}

// ================= shared GEMM mainloop (BM=128, BN=128, BK=16) ==============
// Produces acc[8][8] per thread; rows = row0 + ty*8 + i, cols = col0 + tx*8 + j
#define GEMM_MAINLOOP(A_, B_, M_, N_, K_)                                         \
    float acc[8][8];                                                              \
    _Pragma("unroll") for (int i = 0; i < 8; i++)                                 \
        _Pragma("unroll") for (int j = 0; j < 8; j++) acc[i][j] = 0.f;            \
    const int ar = tid / 4;                                                       \
    const int ac = (tid % 4) * 4;                                                 \
    const int br = tid / 32;                                                      \
    const int bc = (tid % 32) * 4;                                                \
    for (int k0 = 0; k0 < (K_); k0 += 16) {                                       \
        _Pragma("unroll") for (int i = 0; i < 2; i++) {                           \
            int r = row0 + ar + i * 64;                                           \
            float4 v = make_float4(0.f, 0.f, 0.f, 0.f);                           \
            if (r < (M_))                                                         \
                v = *reinterpret_cast<const float4*>(&(A_)[(size_t)r * (K_) + k0 + ac]); \
            As[ac + 0][ar + i * 64] = v.x;                                        \
            As[ac + 1][ar + i * 64] = v.y;                                        \
            As[ac + 2][ar + i * 64] = v.z;                                        \
            As[ac + 3][ar + i * 64] = v.w;                                        \
        }                                                                         \
        _Pragma("unroll") for (int i = 0; i < 2; i++) {                           \
            int r = k0 + br + i * 8;                                              \
            float4 v = *reinterpret_cast<const float4*>(&(B_)[(size_t)r * (N_) + col0 + bc]); \
            *reinterpret_cast<float4*>(&Bs[br + i * 8][bc]) = v;                  \
        }                                                                         \
        __syncthreads();                                                          \
        _Pragma("unroll") for (int k = 0; k < 16; k++) {                          \
            float a[8], b[8];                                                     \
            *reinterpret_cast<float4*>(&a[0]) = *reinterpret_cast<float4*>(&As[k][ty * 8]);     \
            *reinterpret_cast<float4*>(&a[4]) = *reinterpret_cast<float4*>(&As[k][ty * 8 + 4]); \
            *reinterpret_cast<float4*>(&b[0]) = *reinterpret_cast<float4*>(&Bs[k][tx * 8]);     \
            *reinterpret_cast<float4*>(&b[4]) = *reinterpret_cast<float4*>(&Bs[k][tx * 8 + 4]); \
            _Pragma("unroll") for (int i = 0; i < 8; i++)                         \
                _Pragma("unroll") for (int j = 0; j < 8; j++)                     \
                    acc[i][j] += a[i] * b[j];                                     \
        }                                                                         \
        __syncthreads();                                                          \
    }

// ---------------- QKV GEMM: h[M,128] @ Wpk[128,384] -> Q / KV split ----------
__global__ void __launch_bounds__(256, 2)
sgemm_qkv(const float* __restrict__ A, const float* __restrict__ B,
          float* __restrict__ Qout, float* __restrict__ KVout, int M) {
    __shared__ float As[16][128 + 4];
    __shared__ float Bs[16][128];
    const int tid  = threadIdx.x;
    const int tx   = tid % 16;
    const int ty   = tid / 16;
    const int row0 = blockIdx.y * 128;
    const int col0 = blockIdx.x * 128;   // 0 | 128 | 256

    GEMM_MAINLOOP(A, B, M, 384, 128)

#pragma unroll
    for (int i = 0; i < 8; i++) {
        int r = row0 + ty * 8 + i;
        if (r >= M) continue;
        int c = col0 + tx * 8;
#pragma unroll
        for (int jj = 0; jj < 2; jj++) {
            float4 v = make_float4(acc[i][jj * 4 + 0], acc[i][jj * 4 + 1],
                                   acc[i][jj * 4 + 2], acc[i][jj * 4 + 3]);
            int cc = c + jj * 4;
            float* dstp = (cc < D)
                ? &Qout[(size_t)r * D + cc]
                : &KVout[(size_t)r * (2 * D) + (cc - D)];
            *reinterpret_cast<float4*>(dstp) = v;
        }
    }
}

// ---------------- plain GEMM + bias (+relu), for FFN1 ------------------------
template <bool RELU>
__global__ void __launch_bounds__(256, 2)
sgemm128(const float* __restrict__ A, const float* __restrict__ B,
         const float* __restrict__ bias, float* __restrict__ C,
         int M, int N, int K) {
    __shared__ float As[16][128 + 4];
    __shared__ float Bs[16][128];
    const int tid  = threadIdx.x;
    const int tx   = tid % 16;
    const int ty   = tid / 16;
    const int row0 = blockIdx.y * 128;
    const int col0 = blockIdx.x * 128;

    GEMM_MAINLOOP(A, B, M, N, K)

#pragma unroll
    for (int i = 0; i < 8; i++) {
        int r = row0 + ty * 8 + i;
        if (r >= M) continue;
        int c = col0 + tx * 8;
#pragma unroll
        for (int jj = 0; jj < 2; jj++) {
            float4 v = make_float4(acc[i][jj * 4 + 0], acc[i][jj * 4 + 1],
                                   acc[i][jj * 4 + 2], acc[i][jj * 4 + 3]);
            float4 b4 = *reinterpret_cast<const float4*>(&bias[c + jj * 4]);
            v.x += b4.x; v.y += b4.y; v.z += b4.z; v.w += b4.w;
            if (RELU) {
                v.x = fmaxf(v.x, 0.f); v.y = fmaxf(v.y, 0.f);
                v.z = fmaxf(v.z, 0.f); v.w = fmaxf(v.w, 0.f);
            }
            *reinterpret_cast<float4*>(&C[(size_t)r * N + c + jj * 4]) = v;
        }
    }
}

// ---------------- GEMM (N=128) + bias + residual + LayerNorm epilogue --------
// out = LN(res + A@B + bias) * g + b    (grid.x must be 1; N == 128)
__global__ void __launch_bounds__(256, 2)
sgemm_ln(const float* __restrict__ A, const float* __restrict__ B,
         const float* __restrict__ bias, const float* __restrict__ res,
         const float* __restrict__ lng, const float* __restrict__ lnb,
         float* __restrict__ out, int M, int K) {
    __shared__ float As[16][128 + 4];
    __shared__ float Bs[16][128];
    const int tid  = threadIdx.x;
    const int tx   = tid % 16;
    const int ty   = tid / 16;
    const int row0 = blockIdx.y * 128;
    const int col0 = 0;

    GEMM_MAINLOOP(A, B, M, 128, K)

    const int c = tx * 8;
    float4 bia0 = *reinterpret_cast<const float4*>(&bias[c]);
    float4 bia1 = *reinterpret_cast<const float4*>(&bias[c + 4]);
    float4 g0 = *reinterpret_cast<const float4*>(&lng[c]);
    float4 g1 = *reinterpret_cast<const float4*>(&lng[c + 4]);
    float4 bb0 = *reinterpret_cast<const float4*>(&lnb[c]);
    float4 bb1 = *reinterpret_cast<const float4*>(&lnb[c + 4]);

#pragma unroll
    for (int i = 0; i < 8; i++) {
        int r = row0 + ty * 8 + i;
        if (r >= M) continue;   // uniform across the 16-lane tx group
        float4 r0 = *reinterpret_cast<const float4*>(&res[(size_t)r * 128 + c]);
        float4 r1 = *reinterpret_cast<const float4*>(&res[(size_t)r * 128 + c + 4]);
        float v[8];
        v[0] = acc[i][0] + bia0.x + r0.x;
        v[1] = acc[i][1] + bia0.y + r0.y;
        v[2] = acc[i][2] + bia0.z + r0.z;
        v[3] = acc[i][3] + bia0.w + r0.w;
        v[4] = acc[i][4] + bia1.x + r1.x;
        v[5] = acc[i][5] + bia1.y + r1.y;
        v[6] = acc[i][6] + bia1.z + r1.z;
        v[7] = acc[i][7] + bia1.w + r1.w;
        float s = 0.f, s2 = 0.f;
#pragma unroll
        for (int j = 0; j < 8; j++) { s += v[j]; s2 += v[j] * v[j]; }
#pragma unroll
        for (int o = 1; o < 16; o <<= 1) {
            s  += __shfl_xor_sync(0xffffffffu, s,  o);
            s2 += __shfl_xor_sync(0xffffffffu, s2, o);
        }
        float mu   = s * (1.f / 128.f);
        float var  = s2 * (1.f / 128.f) - mu * mu;
        float rstd = rsqrtf(var + 1e-5f);
        float4 o0, o1;
        o0.x = (v[0] - mu) * rstd * g0.x + bb0.x;
        o0.y = (v[1] - mu) * rstd * g0.y + bb0.y;
        o0.z = (v[2] - mu) * rstd * g0.z + bb0.z;
        o0.w = (v[3] - mu) * rstd * g0.w + bb0.w;
        o1.x = (v[4] - mu) * rstd * g1.x + bb1.x;
        o1.y = (v[5] - mu) * rstd * g1.y + bb1.y;
        o1.z = (v[6] - mu) * rstd * g1.z + bb1.z;
        o1.w = (v[7] - mu) * rstd * g1.w + bb1.w;
        *reinterpret_cast<float4*>(&out[(size_t)r * 128 + c])     = o0;
        *reinterpret_cast<float4*>(&out[(size_t)r * 128 + c + 4]) = o1;
    }
}

// ---------------- binning: count / scan / scatter -----------------------------
__global__ void __launch_bounds__(256)
count_kernel(const int* __restrict__ dst, int* __restrict__ cnt) {
    int e = blockIdx.x * blockDim.x + threadIdx.x;
    if (e < NE) atomicAdd(&cnt[dst[e]], 1);
}

__global__ void __launch_bounds__(1024)
scan_kernel(const int* __restrict__ cnt, int* __restrict__ off) {
    __shared__ int s[1024];
    const int t  = threadIdx.x;
    const int CH = (NN + 1023) / 1024;
    const int base = t * CH;
    int sum = 0;
    for (int i = 0; i < CH; i++) {
        int idx = base + i;
        if (idx < NN) sum += cnt[idx];
    }
    s[t] = sum;
    __syncthreads();
    for (int o = 1; o < 1024; o <<= 1) {
        int v = (t >= o) ? s[t - o] : 0;
        __syncthreads();
        s[t] += v;
        __syncthreads();
    }
    int run = (t == 0) ? 0 : s[t - 1];
    for (int i = 0; i < CH; i++) {
        int idx = base + i;
        if (idx < NN) { off[idx] = run; run += cnt[idx]; }
    }
    if (t == 1023) off[NN] = run;
}

__global__ void __launch_bounds__(256)
scatter_kernel(const int* __restrict__ src,
               const int* __restrict__ dst,
               const int* __restrict__ off,
               int* __restrict__ cur,
               int* __restrict__ bin) {
    int e = blockIdx.x * blockDim.x + threadIdx.x;
    if (e >= NE) return;
    int d = dst[e];
    int pos = atomicAdd(&cur[d], 1);
    bin[off[d] + pos] = src[e];
}

// ---------------- aggregation: 1 warp per dst node, no atomics ----------------
__global__ void __launch_bounds__(256)
agg_kernel(const int* __restrict__ off,
           const int* __restrict__ bin,
           const float* __restrict__ Q,
           const float* __restrict__ KV,
           float* __restrict__ head_out) {
    int n = (blockIdx.x * blockDim.x + threadIdx.x) >> 5;
    if (n >= NN) return;
    int lane = threadIdx.x & 31;
    int beg = off[n], end = off[n + 1];

    float4 q = reinterpret_cast<const float4*>(Q + (size_t)n * D)[lane];
    float4 acc = make_float4(0.f, 0.f, 0.f, 0.f);
    float zt = 0.f;

    int s = (beg < end) ? bin[beg] : 0;
    for (int i = beg; i < end; i++) {
        int snext = (i + 1 < end) ? bin[i + 1] : 0;
        const float* sr = KV + (size_t)s * (2 * D);
        float4 kv = reinterpret_cast<const float4*>(sr)[lane];
        float4 vv = reinterpret_cast<const float4*>(sr + D)[lane];
        float p = kv.x * q.x + kv.y * q.y + kv.z * q.z + kv.w * q.w;
        p += __shfl_xor_sync(0xffffffffu, p, 1);
        p += __shfl_xor_sync(0xffffffffu, p, 2);
        float sc = __expf(fminf(5.f, fmaxf(-5.f, p * 0.25f)));
        acc.x += vv.x * sc;
        acc.y += vv.y * sc;
        acc.z += vv.z * sc;
        acc.w += vv.w * sc;
        zt += sc;
        s = snext;
    }
    if (zt > 0.f) {
        float inv = 1.f / zt;
        acc.x *= inv; acc.y *= inv; acc.z *= inv; acc.w *= inv;
    }
    reinterpret_cast<float4*>(head_out + (size_t)n * D)[lane] = acc;
}

// ---------------- launch -----------------------------------------------------
extern "C" void kernel_launch(void* const* d_in, const int* in_sizes, int n_in,
                              void* d_out, int out_size) {
    const float* h   = (const float*)d_in[0];
    const int*   src = (const int*)  d_in[1];
    const int*   dst = (const int*)  d_in[2];
    const float* Wq  = (const float*)d_in[3];
    const float* Wk  = (const float*)d_in[4];
    const float* Wv  = (const float*)d_in[5];
    const float* Wo  = (const float*)d_in[6];
    const float* bo  = (const float*)d_in[7];
    const float* g1  = (const float*)d_in[8];
    const float* b1  = (const float*)d_in[9];
    const float* g2  = (const float*)d_in[10];
    const float* b2  = (const float*)d_in[11];
    const float* W1  = (const float*)d_in[12];
    const float* c1  = (const float*)d_in[13];
    const float* W2  = (const float*)d_in[14];
    const float* c2  = (const float*)d_in[15];
    float* out = (float*)d_out;

    float *Qp, *KVp, *Wpkp, *wVp, *hhp, *tp;
    int *cntp, *offp, *curp, *binp;
    cudaGetSymbolAddress((void**)&Qp,   g_Q);
    cudaGetSymbolAddress((void**)&KVp,  g_KV);
    cudaGetSymbolAddress((void**)&Wpkp, g_Wpk);
    cudaGetSymbolAddress((void**)&wVp,  g_wV);
    cudaGetSymbolAddress((void**)&hhp,  g_hh);
    cudaGetSymbolAddress((void**)&tp,   g_t);
    cudaGetSymbolAddress((void**)&cntp, g_cnt);
    cudaGetSymbolAddress((void**)&offp, g_off);
    cudaGetSymbolAddress((void**)&curp, g_cur);
    cudaGetSymbolAddress((void**)&binp, g_bin);

    // --- binning by dst ---
    cudaMemsetAsync(cntp, 0, NN * sizeof(int));
    cudaMemsetAsync(curp, 0, NN * sizeof(int));
    count_kernel<<<(NE + 255) / 256, 256>>>(dst, cntp);
    scan_kernel<<<1, 1024>>>(cntp, offp);
    scatter_kernel<<<(NE + 255) / 256, 256>>>(src, dst, offp, curp, binp);

    // --- fused QKV GEMM with split outputs ---
    packW_kernel<<<(D * D + 255) / 256, 256>>>(Wq, Wk, Wv, Wpkp);
    {
        dim3 grid(3, (NN + 127) / 128);
        sgemm_qkv<<<grid, 256>>>(h, Wpkp, Qp, KVp, NN);
    }

    // --- attention aggregation (atomic-free) ---
    {
        int blocks = (NN * 32 + 255) / 256;
        agg_kernel<<<blocks, 256>>>(offp, binp, Qp, KVp, wVp);
    }

    // hh = LN(h + head_out @ Wo + bo)   [fused]
    {
        dim3 grid(1, (NN + 127) / 128);
        sgemm_ln<<<grid, 256>>>(wVp, Wo, bo, h, g1, b1, hhp, NN, D);
    }

    // t = relu(hh @ W1 + c1)
    {
        dim3 grid(2, (NN + 127) / 128);
        sgemm128<true><<<grid, 256>>>(hhp, W1, c1, tp, NN, 2 * D, D);
    }

    // out = LN(hh + t @ W2 + c2)   [fused]
    {
        dim3 grid(1, (NN + 127) / 128);
        sgemm_ln<<<grid, 256>>>(tp, W2, c2, hhp, g2, b2, out, NN, 2 * D);
    }
}

// round 7
// speedup vs baseline: 1.9415x; 1.3409x over previous
#include <cuda_runtime.h>
#include <cstdint>

constexpr int NN = 100000;   // nodes
constexpr int NE = 1600000;  // edges
constexpr int D  = 128;
// H=8, DH=16, scale=0.25

// ---------------- scratch ----------------------------------------------------
__device__ float g_Q  [NN * D];        // Q rows (streamed in agg)
__device__ float g_KV [NN * 2 * D];    // per node: [K(128) | V(128)] (gathered)
__device__ float g_Wpk[D * 3 * D];     // packed weights [k][Wq|Wk|Wv]
__device__ float g_wV [NN * D];        // head_out
__device__ float g_hh [NN * D];
__device__ float g_t  [NN * 2 * D];
__device__ int   g_cnt[NN];
__device__ int   g_off[NN + 1];
__device__ int   g_cur[NN];
__device__ int   g_bin[NE];            // src ids binned by dst

// ---------------- helpers -----------------------------------------------------
__device__ __forceinline__ float tf32f(float x) {
    uint32_t r;
    asm("cvt.rna.tf32.f32 %0, %1;" : "=r"(r) : "f"(x));
    return __uint_as_float(r);
}

__device__ __forceinline__ void mma_tf32(float* d, const uint32_t* a, const uint32_t* b) {
    asm volatile(
        "mma.sync.aligned.m16n8k8.row.col.f32.tf32.tf32.f32 "
        "{%0,%1,%2,%3}, {%4,%5,%6,%7}, {%8,%9}, {%0,%1,%2,%3};"
        : "+f"(d[0]), "+f"(d[1]), "+f"(d[2]), "+f"(d[3])
        : "r"(a[0]), "r"(a[1]), "r"(a[2]), "r"(a[3]), "r"(b[0]), "r"(b[1]));
}

// permute k within its 8-group so fragment pairs (k, k+4) become adjacent
__device__ __forceinline__ int kperm(int kl) {
    return ((kl >> 3) << 3) + ((kl & 3) << 1) + ((kl & 7) >> 2);
}

// ---------------- pack Wq|Wk|Wv into [128 x 384] -----------------------------
__global__ void __launch_bounds__(256)
packW_kernel(const float* __restrict__ Wq,
             const float* __restrict__ Wk,
             const float* __restrict__ Wv,
             float* __restrict__ P) {
    int i = blockIdx.x * blockDim.x + threadIdx.x;
    if (i >= D * D) return;
    int k = i / D, c = i % D;
    P[(size_t)k * (3 * D) + c]         = Wq[i];
    P[(size_t)k * (3 * D) + D + c]     = Wk[i];
    P[(size_t)k * (3 * D) + 2 * D + c] = Wv[i];
}

// ================= tf32 tensor-core GEMM, BM=BN=128, BK=16 ===================
// MODE 0: QKV split store (out=Q stride 128, out2=KV stride 256)
// MODE 1: C = relu(A@B + bias), generic N (grid.x = N/128)
// MODE 2: out = LN(res + A@B + bias)*lng + lnb, N==128, grid.x==1
template <int MODE>
__global__ void __launch_bounds__(256, 2)
mma_gemm(const float* __restrict__ A, const float* __restrict__ B,
         const float* __restrict__ bias, const float* __restrict__ res,
         const float* __restrict__ lng, const float* __restrict__ lnb,
         float* __restrict__ out, float* __restrict__ out2,
         int M, int N, int K) {
    constexpr int S = 26;                 // smem row stride (floats, EVEN -> LDS.64 aligned)
    __shared__ __align__(16) float sm[2 * 128 * S];   // As | Bs  (~26.6 KB)
    float* As = sm;
    float* Bs = sm + 128 * S;

    const int tid  = threadIdx.x;
    const int warp = tid >> 5;
    const int lane = tid & 31;
    const int g    = lane >> 2;           // group id (row in fragment)
    const int tg   = lane & 3;            // thread in group
    const int wm   = warp & 3;            // warp m index (4)
    const int wn   = warp >> 2;           // warp n index (2)
    const int row0 = blockIdx.y * 128;
    const int col0 = blockIdx.x * 128;

    float acc[2][8][4];
#pragma unroll
    for (int i = 0; i < 2; i++)
#pragma unroll
        for (int j = 0; j < 8; j++)
#pragma unroll
            for (int q = 0; q < 4; q++) acc[i][j][q] = 0.f;

    for (int k0 = 0; k0 < K; k0 += 16) {
        // ---- A tile: 128 x 16, tf32-convert + permuted store ----
#pragma unroll
        for (int l = 0; l < 2; l++) {
            int fidx = tid + 256 * l;
            int r  = fidx >> 2;
            int kc = (fidx & 3) * 4;
            float4 v = make_float4(0.f, 0.f, 0.f, 0.f);
            if (row0 + r < M)
                v = *reinterpret_cast<const float4*>(&A[(size_t)(row0 + r) * K + k0 + kc]);
            As[r * S + kperm(kc + 0)] = tf32f(v.x);
            As[r * S + kperm(kc + 1)] = tf32f(v.y);
            As[r * S + kperm(kc + 2)] = tf32f(v.z);
            As[r * S + kperm(kc + 3)] = tf32f(v.w);
        }
        // ---- B tile: 16 x 128, transposed into Bs[n][k'] ----
#pragma unroll
        for (int l = 0; l < 2; l++) {
            int fidx = tid + 256 * l;
            int kr = fidx >> 5;
            int nc = (fidx & 31) * 4;
            float4 v = *reinterpret_cast<const float4*>(&B[(size_t)(k0 + kr) * N + col0 + nc]);
            int kp = kperm(kr);
            Bs[(nc + 0) * S + kp] = tf32f(v.x);
            Bs[(nc + 1) * S + kp] = tf32f(v.y);
            Bs[(nc + 2) * S + kp] = tf32f(v.z);
            Bs[(nc + 3) * S + kp] = tf32f(v.w);
        }
        __syncthreads();

#pragma unroll
        for (int ks = 0; ks < 2; ks++) {
            uint32_t af[2][4];
#pragma unroll
            for (int i = 0; i < 2; i++) {
                int rb = 32 * wm + 16 * i + g;
                float2 lo = *reinterpret_cast<float2*>(&As[rb * S + ks * 8 + 2 * tg]);
                float2 hi = *reinterpret_cast<float2*>(&As[(rb + 8) * S + ks * 8 + 2 * tg]);
                af[i][0] = __float_as_uint(lo.x);
                af[i][1] = __float_as_uint(hi.x);
                af[i][2] = __float_as_uint(lo.y);
                af[i][3] = __float_as_uint(hi.y);
            }
#pragma unroll
            for (int j = 0; j < 8; j++) {
                int nb = 64 * wn + 8 * j + g;
                float2 bv = *reinterpret_cast<float2*>(&Bs[nb * S + ks * 8 + 2 * tg]);
                uint32_t bf[2] = {__float_as_uint(bv.x), __float_as_uint(bv.y)};
                mma_tf32(acc[0][j], af[0], bf);
                mma_tf32(acc[1][j], af[1], bf);
            }
        }
        __syncthreads();
    }

    // =================== epilogues ===================
    if (MODE == 0) {
        float* baseO;
        int strideO, coff;
        if (blockIdx.x == 0) { baseO = out;  strideO = 128; coff = 0; }
        else                 { baseO = out2; strideO = 256; coff = (blockIdx.x - 1) * 128; }
#pragma unroll
        for (int i = 0; i < 2; i++) {
            int rl = row0 + 32 * wm + 16 * i + g;
            int rh = rl + 8;
#pragma unroll
            for (int j = 0; j < 8; j++) {
                int lc = 64 * wn + 8 * j + 2 * tg;
                if (rl < M)
                    *reinterpret_cast<float2*>(&baseO[(size_t)rl * strideO + coff + lc]) =
                        make_float2(acc[i][j][0], acc[i][j][1]);
                if (rh < M)
                    *reinterpret_cast<float2*>(&baseO[(size_t)rh * strideO + coff + lc]) =
                        make_float2(acc[i][j][2], acc[i][j][3]);
            }
        }
    } else if (MODE == 1) {
#pragma unroll
        for (int i = 0; i < 2; i++) {
            int rl = row0 + 32 * wm + 16 * i + g;
            int rh = rl + 8;
#pragma unroll
            for (int j = 0; j < 8; j++) {
                int c = col0 + 64 * wn + 8 * j + 2 * tg;
                float2 bb = *reinterpret_cast<const float2*>(&bias[c]);
                float2 v0 = make_float2(fmaxf(acc[i][j][0] + bb.x, 0.f),
                                        fmaxf(acc[i][j][1] + bb.y, 0.f));
                float2 v1 = make_float2(fmaxf(acc[i][j][2] + bb.x, 0.f),
                                        fmaxf(acc[i][j][3] + bb.y, 0.f));
                if (rl < M) *reinterpret_cast<float2*>(&out[(size_t)rl * N + c]) = v0;
                if (rh < M) *reinterpret_cast<float2*>(&out[(size_t)rh * N + c]) = v1;
            }
        }
    } else {
        // MODE 2: bias + residual + LayerNorm (N == 128, grid.x == 1)
        float sl[2][2], s2l[2][2];
#pragma unroll
        for (int i = 0; i < 2; i++)
            for (int hf = 0; hf < 2; hf++) { sl[i][hf] = 0.f; s2l[i][hf] = 0.f; }

#pragma unroll
        for (int i = 0; i < 2; i++) {
            int rl = row0 + 32 * wm + 16 * i + g;
            int rh = rl + 8;
#pragma unroll
            for (int j = 0; j < 8; j++) {
                int c = 64 * wn + 8 * j + 2 * tg;
                float2 bb = *reinterpret_cast<const float2*>(&bias[c]);
                float2 r0 = make_float2(0.f, 0.f), r1 = make_float2(0.f, 0.f);
                if (rl < M) r0 = *reinterpret_cast<const float2*>(&res[(size_t)rl * 128 + c]);
                if (rh < M) r1 = *reinterpret_cast<const float2*>(&res[(size_t)rh * 128 + c]);
                acc[i][j][0] += bb.x + r0.x;
                acc[i][j][1] += bb.y + r0.y;
                acc[i][j][2] += bb.x + r1.x;
                acc[i][j][3] += bb.y + r1.y;
                sl[i][0]  += acc[i][j][0] + acc[i][j][1];
                s2l[i][0] += acc[i][j][0] * acc[i][j][0] + acc[i][j][1] * acc[i][j][1];
                sl[i][1]  += acc[i][j][2] + acc[i][j][3];
                s2l[i][1] += acc[i][j][2] * acc[i][j][2] + acc[i][j][3] * acc[i][j][3];
            }
        }
        // reduce across the 4 lanes of each row group
#pragma unroll
        for (int i = 0; i < 2; i++)
#pragma unroll
            for (int hf = 0; hf < 2; hf++) {
#pragma unroll
                for (int o = 1; o < 4; o <<= 1) {
                    sl[i][hf]  += __shfl_xor_sync(0xffffffffu, sl[i][hf],  o);
                    s2l[i][hf] += __shfl_xor_sync(0xffffffffu, s2l[i][hf], o);
                }
            }
        // cross-warp (wn=0 vs wn=1) reduction via smem (reuse tile buffer)
        __syncthreads();
        float2* sbuf = reinterpret_cast<float2*>(sm);
        if (tg == 0) {
#pragma unroll
            for (int i = 0; i < 2; i++) {
                int rloc = 32 * wm + 16 * i + g;
                sbuf[wn * 128 + rloc]     = make_float2(sl[i][0], s2l[i][0]);
                sbuf[wn * 128 + rloc + 8] = make_float2(sl[i][1], s2l[i][1]);
            }
        }
        __syncthreads();
        float mu[2][2], rstd[2][2];
#pragma unroll
        for (int i = 0; i < 2; i++)
#pragma unroll
            for (int hf = 0; hf < 2; hf++) {
                int rloc = 32 * wm + 16 * i + g + hf * 8;
                float2 p0 = sbuf[rloc];
                float2 p1 = sbuf[128 + rloc];
                float s  = p0.x + p1.x;
                float s2 = p0.y + p1.y;
                float m  = s * (1.f / 128.f);
                float var = s2 * (1.f / 128.f) - m * m;
                mu[i][hf]   = m;
                rstd[i][hf] = rsqrtf(var + 1e-5f);
            }
#pragma unroll
        for (int i = 0; i < 2; i++) {
            int rl = row0 + 32 * wm + 16 * i + g;
            int rh = rl + 8;
#pragma unroll
            for (int j = 0; j < 8; j++) {
                int c = 64 * wn + 8 * j + 2 * tg;
                float2 gg = *reinterpret_cast<const float2*>(&lng[c]);
                float2 bb = *reinterpret_cast<const float2*>(&lnb[c]);
                if (rl < M) {
                    float2 o0;
                    o0.x = (acc[i][j][0] - mu[i][0]) * rstd[i][0] * gg.x + bb.x;
                    o0.y = (acc[i][j][1] - mu[i][0]) * rstd[i][0] * gg.y + bb.y;
                    *reinterpret_cast<float2*>(&out[(size_t)rl * 128 + c]) = o0;
                }
                if (rh < M) {
                    float2 o1;
                    o1.x = (acc[i][j][2] - mu[i][1]) * rstd[i][1] * gg.x + bb.x;
                    o1.y = (acc[i][j][3] - mu[i][1]) * rstd[i][1] * gg.y + bb.y;
                    *reinterpret_cast<float2*>(&out[(size_t)rh * 128 + c]) = o1;
                }
            }
        }
    }
}

// ---------------- binning: count / scan / scatter -----------------------------
__global__ void __launch_bounds__(256)
count_kernel(const int* __restrict__ dst, int* __restrict__ cnt) {
    int e = blockIdx.x * blockDim.x + threadIdx.x;
    if (e < NE) atomicAdd(&cnt[dst[e]], 1);
}

__global__ void __launch_bounds__(1024)
scan_kernel(const int* __restrict__ cnt, int* __restrict__ off) {
    __shared__ int s[1024];
    const int t  = threadIdx.x;
    const int CH = (NN + 1023) / 1024;
    const int base = t * CH;
    int sum = 0;
    for (int i = 0; i < CH; i++) {
        int idx = base + i;
        if (idx < NN) sum += cnt[idx];
    }
    s[t] = sum;
    __syncthreads();
    for (int o = 1; o < 1024; o <<= 1) {
        int v = (t >= o) ? s[t - o] : 0;
        __syncthreads();
        s[t] += v;
        __syncthreads();
    }
    int run = (t == 0) ? 0 : s[t - 1];
    for (int i = 0; i < CH; i++) {
        int idx = base + i;
        if (idx < NN) { off[idx] = run; run += cnt[idx]; }
    }
    if (t == 1023) off[NN] = run;
}

__global__ void __launch_bounds__(256)
scatter_kernel(const int* __restrict__ src,
               const int* __restrict__ dst,
               const int* __restrict__ off,
               int* __restrict__ cur,
               int* __restrict__ bin) {
    int e = blockIdx.x * blockDim.x + threadIdx.x;
    if (e >= NE) return;
    int d = dst[e];
    int pos = atomicAdd(&cur[d], 1);
    bin[off[d] + pos] = src[e];
}

// ---------------- aggregation: 1 warp per dst node, no atomics ----------------
__global__ void __launch_bounds__(256)
agg_kernel(const int* __restrict__ off,
           const int* __restrict__ bin,
           const float* __restrict__ Q,
           const float* __restrict__ KV,
           float* __restrict__ head_out) {
    int n = (blockIdx.x * blockDim.x + threadIdx.x) >> 5;
    if (n >= NN) return;
    int lane = threadIdx.x & 31;
    int beg = off[n], end = off[n + 1];

    float4 q = reinterpret_cast<const float4*>(Q + (size_t)n * D)[lane];
    float4 acc = make_float4(0.f, 0.f, 0.f, 0.f);
    float zt = 0.f;

    int s = (beg < end) ? bin[beg] : 0;
    for (int i = beg; i < end; i++) {
        int snext = (i + 1 < end) ? bin[i + 1] : 0;
        const float* sr = KV + (size_t)s * (2 * D);
        float4 kv = reinterpret_cast<const float4*>(sr)[lane];
        float4 vv = reinterpret_cast<const float4*>(sr + D)[lane];
        float p = kv.x * q.x + kv.y * q.y + kv.z * q.z + kv.w * q.w;
        p += __shfl_xor_sync(0xffffffffu, p, 1);
        p += __shfl_xor_sync(0xffffffffu, p, 2);
        float sc = __expf(fminf(5.f, fmaxf(-5.f, p * 0.25f)));
        acc.x += vv.x * sc;
        acc.y += vv.y * sc;
        acc.z += vv.z * sc;
        acc.w += vv.w * sc;
        zt += sc;
        s = snext;
    }
    if (zt > 0.f) {
        float inv = 1.f / zt;
        acc.x *= inv; acc.y *= inv; acc.z *= inv; acc.w *= inv;
    }
    reinterpret_cast<float4*>(head_out + (size_t)n * D)[lane] = acc;
}

// ---------------- launch -----------------------------------------------------
extern "C" void kernel_launch(void* const* d_in, const int* in_sizes, int n_in,
                              void* d_out, int out_size) {
    const float* h   = (const float*)d_in[0];
    const int*   src = (const int*)  d_in[1];
    const int*   dst = (const int*)  d_in[2];
    const float* Wq  = (const float*)d_in[3];
    const float* Wk  = (const float*)d_in[4];
    const float* Wv  = (const float*)d_in[5];
    const float* Wo  = (const float*)d_in[6];
    const float* bo  = (const float*)d_in[7];
    const float* g1  = (const float*)d_in[8];
    const float* b1  = (const float*)d_in[9];
    const float* g2  = (const float*)d_in[10];
    const float* b2  = (const float*)d_in[11];
    const float* W1  = (const float*)d_in[12];
    const float* c1  = (const float*)d_in[13];
    const float* W2  = (const float*)d_in[14];
    const float* c2  = (const float*)d_in[15];
    float* out = (float*)d_out;

    float *Qp, *KVp, *Wpkp, *wVp, *hhp, *tp;
    int *cntp, *offp, *curp, *binp;
    cudaGetSymbolAddress((void**)&Qp,   g_Q);
    cudaGetSymbolAddress((void**)&KVp,  g_KV);
    cudaGetSymbolAddress((void**)&Wpkp, g_Wpk);
    cudaGetSymbolAddress((void**)&wVp,  g_wV);
    cudaGetSymbolAddress((void**)&hhp,  g_hh);
    cudaGetSymbolAddress((void**)&tp,   g_t);
    cudaGetSymbolAddress((void**)&cntp, g_cnt);
    cudaGetSymbolAddress((void**)&offp, g_off);
    cudaGetSymbolAddress((void**)&curp, g_cur);
    cudaGetSymbolAddress((void**)&binp, g_bin);

    const int GY = (NN + 127) / 128;   // 782

    // --- binning by dst ---
    cudaMemsetAsync(cntp, 0, NN * sizeof(int));
    cudaMemsetAsync(curp, 0, NN * sizeof(int));
    count_kernel<<<(NE + 255) / 256, 256>>>(dst, cntp);
    scan_kernel<<<1, 1024>>>(cntp, offp);
    scatter_kernel<<<(NE + 255) / 256, 256>>>(src, dst, offp, curp, binp);

    // --- fused QKV GEMM (tf32 tensor cores), split Q / KV outputs ---
    packW_kernel<<<(D * D + 255) / 256, 256>>>(Wq, Wk, Wv, Wpkp);
    mma_gemm<0><<<dim3(3, GY), 256>>>(h, Wpkp, nullptr, nullptr, nullptr, nullptr,
                                      Qp, KVp, NN, 3 * D, D);

    // --- attention aggregation (atomic-free) ---
    {
        int blocks = (NN * 32 + 255) / 256;
        agg_kernel<<<blocks, 256>>>(offp, binp, Qp, KVp, wVp);
    }

    // hh = LN(h + head_out @ Wo + bo)
    mma_gemm<2><<<dim3(1, GY), 256>>>(wVp, Wo, bo, h, g1, b1,
                                      hhp, nullptr, NN, D, D);

    // t = relu(hh @ W1 + c1)
    mma_gemm<1><<<dim3(2, GY), 256>>>(hhp, W1, c1, nullptr, nullptr, nullptr,
                                      tp, nullptr, NN, 2 * D, D);

    // out = LN(hh + t @ W2 + c2)
    mma_gemm<2><<<dim3(1, GY), 256>>>(tp, W2, c2, hhp, g2, b2,
                                      out, nullptr, NN, D, 2 * D);
}

// round 8
// speedup vs baseline: 1.9929x; 1.0265x over previous
#include <cuda_runtime.h>
#include <cuda_fp16.h>
#include <cstdint>

constexpr int NN = 100000;   // nodes
constexpr int NE = 1600000;  // edges
constexpr int D  = 128;
// H=8, DH=16, scale=0.25

// ---------------- scratch ----------------------------------------------------
__device__ float  g_Q  [NN * D];        // Q rows fp32 (streamed in agg)
__device__ __half g_KVh[NN * 2 * D];    // per node: [K(128) | V(128)] fp16 (gathered)
__device__ float  g_Wpk[D * 3 * D];     // packed weights [k][Wq|Wk|Wv]
__device__ float  g_wV [NN * D];        // head_out
__device__ float  g_hh [NN * D];
__device__ float  g_t  [NN * 2 * D];
__device__ int    g_cnt[NN];
__device__ int    g_off[NN + 1];
__device__ int    g_cur[NN];
__device__ int    g_bin[NE];            // src ids binned by dst

// ---------------- helpers -----------------------------------------------------
__device__ __forceinline__ float tf32f(float x) {
    uint32_t r;
    asm("cvt.rna.tf32.f32 %0, %1;" : "=r"(r) : "f"(x));
    return __uint_as_float(r);
}

__device__ __forceinline__ void mma_tf32(float* d, const uint32_t* a, const uint32_t* b) {
    asm volatile(
        "mma.sync.aligned.m16n8k8.row.col.f32.tf32.tf32.f32 "
        "{%0,%1,%2,%3}, {%4,%5,%6,%7}, {%8,%9}, {%0,%1,%2,%3};"
        : "+f"(d[0]), "+f"(d[1]), "+f"(d[2]), "+f"(d[3])
        : "r"(a[0]), "r"(a[1]), "r"(a[2]), "r"(a[3]), "r"(b[0]), "r"(b[1]));
}

// permute k within its 8-group so fragment pairs (k, k+4) become adjacent
__device__ __forceinline__ int kperm(int kl) {
    return ((kl >> 3) << 3) + ((kl & 3) << 1) + ((kl & 7) >> 2);
}

// ---------------- pack Wq|Wk|Wv into [128 x 384] -----------------------------
__global__ void __launch_bounds__(256)
packW_kernel(const float* __restrict__ Wq,
             const float* __restrict__ Wk,
             const float* __restrict__ Wv,
             float* __restrict__ P) {
    int i = blockIdx.x * blockDim.x + threadIdx.x;
    if (i >= D * D) return;
    int k = i / D, c = i % D;
    P[(size_t)k * (3 * D) + c]         = Wq[i];
    P[(size_t)k * (3 * D) + D + c]     = Wk[i];
    P[(size_t)k * (3 * D) + 2 * D + c] = Wv[i];
}

// ================= tf32 tensor-core GEMM, BM=BN=128, BK=16 ===================
// MODE 0: QKV split store (out=Q fp32 stride 128; out2=KV fp16 stride 256)
// MODE 1: C = relu(A@B + bias), generic N (grid.x = N/128)
// MODE 2: out = LN(res + A@B + bias)*lng + lnb, N==128, grid.x==1
template <int MODE>
__global__ void __launch_bounds__(256, 2)
mma_gemm(const float* __restrict__ A, const float* __restrict__ B,
         const float* __restrict__ bias, const float* __restrict__ res,
         const float* __restrict__ lng, const float* __restrict__ lnb,
         float* __restrict__ out, __half* __restrict__ out2,
         int M, int N, int K) {
    constexpr int S = 26;                 // smem row stride (floats, EVEN -> LDS.64 aligned)
    __shared__ __align__(16) float sm[2 * 128 * S];
    float* As = sm;
    float* Bs = sm + 128 * S;

    const int tid  = threadIdx.x;
    const int warp = tid >> 5;
    const int lane = tid & 31;
    const int g    = lane >> 2;
    const int tg   = lane & 3;
    const int wm   = warp & 3;
    const int wn   = warp >> 2;
    const int row0 = blockIdx.y * 128;
    const int col0 = blockIdx.x * 128;

    float acc[2][8][4];
#pragma unroll
    for (int i = 0; i < 2; i++)
#pragma unroll
        for (int j = 0; j < 8; j++)
#pragma unroll
            for (int q = 0; q < 4; q++) acc[i][j][q] = 0.f;

    for (int k0 = 0; k0 < K; k0 += 16) {
#pragma unroll
        for (int l = 0; l < 2; l++) {
            int fidx = tid + 256 * l;
            int r  = fidx >> 2;
            int kc = (fidx & 3) * 4;
            float4 v = make_float4(0.f, 0.f, 0.f, 0.f);
            if (row0 + r < M)
                v = *reinterpret_cast<const float4*>(&A[(size_t)(row0 + r) * K + k0 + kc]);
            As[r * S + kperm(kc + 0)] = tf32f(v.x);
            As[r * S + kperm(kc + 1)] = tf32f(v.y);
            As[r * S + kperm(kc + 2)] = tf32f(v.z);
            As[r * S + kperm(kc + 3)] = tf32f(v.w);
        }
#pragma unroll
        for (int l = 0; l < 2; l++) {
            int fidx = tid + 256 * l;
            int kr = fidx >> 5;
            int nc = (fidx & 31) * 4;
            float4 v = *reinterpret_cast<const float4*>(&B[(size_t)(k0 + kr) * N + col0 + nc]);
            int kp = kperm(kr);
            Bs[(nc + 0) * S + kp] = tf32f(v.x);
            Bs[(nc + 1) * S + kp] = tf32f(v.y);
            Bs[(nc + 2) * S + kp] = tf32f(v.z);
            Bs[(nc + 3) * S + kp] = tf32f(v.w);
        }
        __syncthreads();

#pragma unroll
        for (int ks = 0; ks < 2; ks++) {
            uint32_t af[2][4];
#pragma unroll
            for (int i = 0; i < 2; i++) {
                int rb = 32 * wm + 16 * i + g;
                float2 lo = *reinterpret_cast<float2*>(&As[rb * S + ks * 8 + 2 * tg]);
                float2 hi = *reinterpret_cast<float2*>(&As[(rb + 8) * S + ks * 8 + 2 * tg]);
                af[i][0] = __float_as_uint(lo.x);
                af[i][1] = __float_as_uint(hi.x);
                af[i][2] = __float_as_uint(lo.y);
                af[i][3] = __float_as_uint(hi.y);
            }
#pragma unroll
            for (int j = 0; j < 8; j++) {
                int nb = 64 * wn + 8 * j + g;
                float2 bv = *reinterpret_cast<float2*>(&Bs[nb * S + ks * 8 + 2 * tg]);
                uint32_t bf[2] = {__float_as_uint(bv.x), __float_as_uint(bv.y)};
                mma_tf32(acc[0][j], af[0], bf);
                mma_tf32(acc[1][j], af[1], bf);
            }
        }
        __syncthreads();
    }

    // =================== epilogues ===================
    if (MODE == 0) {
        if (blockIdx.x == 0) {
            // Q: fp32, stride 128
#pragma unroll
            for (int i = 0; i < 2; i++) {
                int rl = row0 + 32 * wm + 16 * i + g;
                int rh = rl + 8;
#pragma unroll
                for (int j = 0; j < 8; j++) {
                    int lc = 64 * wn + 8 * j + 2 * tg;
                    if (rl < M)
                        *reinterpret_cast<float2*>(&out[(size_t)rl * 128 + lc]) =
                            make_float2(acc[i][j][0], acc[i][j][1]);
                    if (rh < M)
                        *reinterpret_cast<float2*>(&out[(size_t)rh * 128 + lc]) =
                            make_float2(acc[i][j][2], acc[i][j][3]);
                }
            }
        } else {
            // K (bx=1) / V (bx=2): fp16, node stride 256 halves
            int coff = (blockIdx.x - 1) * 128;
#pragma unroll
            for (int i = 0; i < 2; i++) {
                int rl = row0 + 32 * wm + 16 * i + g;
                int rh = rl + 8;
#pragma unroll
                for (int j = 0; j < 8; j++) {
                    int lc = coff + 64 * wn + 8 * j + 2 * tg;
                    if (rl < M)
                        *reinterpret_cast<__half2*>(&out2[(size_t)rl * 256 + lc]) =
                            __floats2half2_rn(acc[i][j][0], acc[i][j][1]);
                    if (rh < M)
                        *reinterpret_cast<__half2*>(&out2[(size_t)rh * 256 + lc]) =
                            __floats2half2_rn(acc[i][j][2], acc[i][j][3]);
                }
            }
        }
    } else if (MODE == 1) {
#pragma unroll
        for (int i = 0; i < 2; i++) {
            int rl = row0 + 32 * wm + 16 * i + g;
            int rh = rl + 8;
#pragma unroll
            for (int j = 0; j < 8; j++) {
                int c = col0 + 64 * wn + 8 * j + 2 * tg;
                float2 bb = *reinterpret_cast<const float2*>(&bias[c]);
                float2 v0 = make_float2(fmaxf(acc[i][j][0] + bb.x, 0.f),
                                        fmaxf(acc[i][j][1] + bb.y, 0.f));
                float2 v1 = make_float2(fmaxf(acc[i][j][2] + bb.x, 0.f),
                                        fmaxf(acc[i][j][3] + bb.y, 0.f));
                if (rl < M) *reinterpret_cast<float2*>(&out[(size_t)rl * N + c]) = v0;
                if (rh < M) *reinterpret_cast<float2*>(&out[(size_t)rh * N + c]) = v1;
            }
        }
    } else {
        // MODE 2: bias + residual + LayerNorm (N == 128, grid.x == 1)
        float sl[2][2], s2l[2][2];
#pragma unroll
        for (int i = 0; i < 2; i++)
            for (int hf = 0; hf < 2; hf++) { sl[i][hf] = 0.f; s2l[i][hf] = 0.f; }

#pragma unroll
        for (int i = 0; i < 2; i++) {
            int rl = row0 + 32 * wm + 16 * i + g;
            int rh = rl + 8;
#pragma unroll
            for (int j = 0; j < 8; j++) {
                int c = 64 * wn + 8 * j + 2 * tg;
                float2 bb = *reinterpret_cast<const float2*>(&bias[c]);
                float2 r0 = make_float2(0.f, 0.f), r1 = make_float2(0.f, 0.f);
                if (rl < M) r0 = *reinterpret_cast<const float2*>(&res[(size_t)rl * 128 + c]);
                if (rh < M) r1 = *reinterpret_cast<const float2*>(&res[(size_t)rh * 128 + c]);
                acc[i][j][0] += bb.x + r0.x;
                acc[i][j][1] += bb.y + r0.y;
                acc[i][j][2] += bb.x + r1.x;
                acc[i][j][3] += bb.y + r1.y;
                sl[i][0]  += acc[i][j][0] + acc[i][j][1];
                s2l[i][0] += acc[i][j][0] * acc[i][j][0] + acc[i][j][1] * acc[i][j][1];
                sl[i][1]  += acc[i][j][2] + acc[i][j][3];
                s2l[i][1] += acc[i][j][2] * acc[i][j][2] + acc[i][j][3] * acc[i][j][3];
            }
        }
#pragma unroll
        for (int i = 0; i < 2; i++)
#pragma unroll
            for (int hf = 0; hf < 2; hf++) {
#pragma unroll
                for (int o = 1; o < 4; o <<= 1) {
                    sl[i][hf]  += __shfl_xor_sync(0xffffffffu, sl[i][hf],  o);
                    s2l[i][hf] += __shfl_xor_sync(0xffffffffu, s2l[i][hf], o);
                }
            }
        __syncthreads();
        float2* sbuf = reinterpret_cast<float2*>(sm);
        if (tg == 0) {
#pragma unroll
            for (int i = 0; i < 2; i++) {
                int rloc = 32 * wm + 16 * i + g;
                sbuf[wn * 128 + rloc]     = make_float2(sl[i][0], s2l[i][0]);
                sbuf[wn * 128 + rloc + 8] = make_float2(sl[i][1], s2l[i][1]);
            }
        }
        __syncthreads();
        float mu[2][2], rstd[2][2];
#pragma unroll
        for (int i = 0; i < 2; i++)
#pragma unroll
            for (int hf = 0; hf < 2; hf++) {
                int rloc = 32 * wm + 16 * i + g + hf * 8;
                float2 p0 = sbuf[rloc];
                float2 p1 = sbuf[128 + rloc];
                float s  = p0.x + p1.x;
                float s2 = p0.y + p1.y;
                float m  = s * (1.f / 128.f);
                float var = s2 * (1.f / 128.f) - m * m;
                mu[i][hf]   = m;
                rstd[i][hf] = rsqrtf(var + 1e-5f);
            }
#pragma unroll
        for (int i = 0; i < 2; i++) {
            int rl = row0 + 32 * wm + 16 * i + g;
            int rh = rl + 8;
#pragma unroll
            for (int j = 0; j < 8; j++) {
                int c = 64 * wn + 8 * j + 2 * tg;
                float2 gg = *reinterpret_cast<const float2*>(&lng[c]);
                float2 bb = *reinterpret_cast<const float2*>(&lnb[c]);
                if (rl < M) {
                    float2 o0;
                    o0.x = (acc[i][j][0] - mu[i][0]) * rstd[i][0] * gg.x + bb.x;
                    o0.y = (acc[i][j][1] - mu[i][0]) * rstd[i][0] * gg.y + bb.y;
                    *reinterpret_cast<float2*>(&out[(size_t)rl * 128 + c]) = o0;
                }
                if (rh < M) {
                    float2 o1;
                    o1.x = (acc[i][j][2] - mu[i][1]) * rstd[i][1] * gg.x + bb.x;
                    o1.y = (acc[i][j][3] - mu[i][1]) * rstd[i][1] * gg.y + bb.y;
                    *reinterpret_cast<float2*>(&out[(size_t)rh * 128 + c]) = o1;
                }
            }
        }
    }
}

// ---------------- binning: count / scan / scatter -----------------------------
__global__ void __launch_bounds__(256)
count_kernel(const int* __restrict__ dst, int* __restrict__ cnt) {
    int e = blockIdx.x * blockDim.x + threadIdx.x;
    if (e < NE) atomicAdd(&cnt[dst[e]], 1);
}

__global__ void __launch_bounds__(1024)
scan_kernel(const int* __restrict__ cnt, int* __restrict__ off) {
    __shared__ int s[1024];
    const int t  = threadIdx.x;
    const int CH = (NN + 1023) / 1024;
    const int base = t * CH;
    int sum = 0;
    for (int i = 0; i < CH; i++) {
        int idx = base + i;
        if (idx < NN) sum += cnt[idx];
    }
    s[t] = sum;
    __syncthreads();
    for (int o = 1; o < 1024; o <<= 1) {
        int v = (t >= o) ? s[t - o] : 0;
        __syncthreads();
        s[t] += v;
        __syncthreads();
    }
    int run = (t == 0) ? 0 : s[t - 1];
    for (int i = 0; i < CH; i++) {
        int idx = base + i;
        if (idx < NN) { off[idx] = run; run += cnt[idx]; }
    }
    if (t == 1023) off[NN] = run;
}

__global__ void __launch_bounds__(256)
scatter_kernel(const int* __restrict__ src,
               const int* __restrict__ dst,
               const int* __restrict__ off,
               int* __restrict__ cur,
               int* __restrict__ bin) {
    int e = blockIdx.x * blockDim.x + threadIdx.x;
    if (e >= NE) return;
    int d = dst[e];
    int pos = atomicAdd(&cur[d], 1);
    bin[off[d] + pos] = src[e];
}

// ---------------- aggregation: 1 warp / node, fp16 KV, split-warp -------------
// lanes 0-15: K·Q dot per 8 cols; lanes 16-31: V accumulate per 8 cols.
__global__ void __launch_bounds__(256)
agg_kernel(const int* __restrict__ off,
           const int* __restrict__ bin,
           const float* __restrict__ Q,
           const __half* __restrict__ KV,
           float* __restrict__ head_out) {
    int n = (blockIdx.x * blockDim.x + threadIdx.x) >> 5;
    if (n >= NN) return;
    const int lane = threadIdx.x & 31;
    const int l16  = lane & 15;
    const int srcl = l16 & ~1;          // even lane of the head pair
    int beg = off[n], end = off[n + 1];

    // lower lanes preload Q cols 8*l16 .. 8*l16+7
    float q[8];
    if (lane < 16) {
        float4 qa = *reinterpret_cast<const float4*>(&Q[(size_t)n * D + 8 * l16]);
        float4 qb = *reinterpret_cast<const float4*>(&Q[(size_t)n * D + 8 * l16 + 4]);
        q[0] = qa.x; q[1] = qa.y; q[2] = qa.z; q[3] = qa.w;
        q[4] = qb.x; q[5] = qb.y; q[6] = qb.z; q[7] = qb.w;
    }

    float acc[8];
#pragma unroll
    for (int j = 0; j < 8; j++) acc[j] = 0.f;
    float zt = 0.f;

    int s = (beg < end) ? bin[beg] : 0;
    for (int i = beg; i < end; i++) {
        int snext = (i + 1 < end) ? bin[i + 1] : 0;
        // 16 B per lane: lanes 0-15 cover K row, lanes 16-31 cover V row
        uint4 raw = *reinterpret_cast<const uint4*>(KV + (size_t)s * 256 + lane * 8);
        float2 f0 = __half22float2(*reinterpret_cast<__half2*>(&raw.x));
        float2 f1 = __half22float2(*reinterpret_cast<__half2*>(&raw.y));
        float2 f2 = __half22float2(*reinterpret_cast<__half2*>(&raw.z));
        float2 f3 = __half22float2(*reinterpret_cast<__half2*>(&raw.w));

        // lower-lane dot (garbage in upper lanes, unused)
        float p = f0.x * q[0] + f0.y * q[1] + f1.x * q[2] + f1.y * q[3]
                + f2.x * q[4] + f2.y * q[5] + f3.x * q[6] + f3.y * q[7];
        p += __shfl_xor_sync(0xffffffffu, p, 1);   // full 16-elem head dot
        float sc = __expf(fminf(5.f, fmaxf(-5.f, p * 0.25f)));
        zt += sc;                                   // valid in lower lanes
        float sc_v = __shfl_sync(0xffffffffu, sc, srcl);  // broadcast to V lanes

        if (lane >= 16) {
            acc[0] += f0.x * sc_v; acc[1] += f0.y * sc_v;
            acc[2] += f1.x * sc_v; acc[3] += f1.y * sc_v;
            acc[4] += f2.x * sc_v; acc[5] += f2.y * sc_v;
            acc[6] += f3.x * sc_v; acc[7] += f3.y * sc_v;
        }
        s = snext;
    }

    // upper lanes: divide by z of their head and store cols 8*l16..8*l16+7
    float ztv = __shfl_sync(0xffffffffu, zt, srcl);
    if (lane >= 16) {
        if (ztv > 0.f) {
            float inv = 1.f / ztv;
#pragma unroll
            for (int j = 0; j < 8; j++) acc[j] *= inv;
        }
        float* op = head_out + (size_t)n * D + 8 * l16;
        *reinterpret_cast<float4*>(op)     = make_float4(acc[0], acc[1], acc[2], acc[3]);
        *reinterpret_cast<float4*>(op + 4) = make_float4(acc[4], acc[5], acc[6], acc[7]);
    }
}

// ---------------- launch -----------------------------------------------------
extern "C" void kernel_launch(void* const* d_in, const int* in_sizes, int n_in,
                              void* d_out, int out_size) {
    const float* h   = (const float*)d_in[0];
    const int*   src = (const int*)  d_in[1];
    const int*   dst = (const int*)  d_in[2];
    const float* Wq  = (const float*)d_in[3];
    const float* Wk  = (const float*)d_in[4];
    const float* Wv  = (const float*)d_in[5];
    const float* Wo  = (const float*)d_in[6];
    const float* bo  = (const float*)d_in[7];
    const float* g1  = (const float*)d_in[8];
    const float* b1  = (const float*)d_in[9];
    const float* g2  = (const float*)d_in[10];
    const float* b2  = (const float*)d_in[11];
    const float* W1  = (const float*)d_in[12];
    const float* c1  = (const float*)d_in[13];
    const float* W2  = (const float*)d_in[14];
    const float* c2  = (const float*)d_in[15];
    float* out = (float*)d_out;

    float *Qp, *Wpkp, *wVp, *hhp, *tp;
    __half* KVp;
    int *cntp, *offp, *curp, *binp;
    cudaGetSymbolAddress((void**)&Qp,   g_Q);
    cudaGetSymbolAddress((void**)&KVp,  g_KVh);
    cudaGetSymbolAddress((void**)&Wpkp, g_Wpk);
    cudaGetSymbolAddress((void**)&wVp,  g_wV);
    cudaGetSymbolAddress((void**)&hhp,  g_hh);
    cudaGetSymbolAddress((void**)&tp,   g_t);
    cudaGetSymbolAddress((void**)&cntp, g_cnt);
    cudaGetSymbolAddress((void**)&offp, g_off);
    cudaGetSymbolAddress((void**)&curp, g_cur);
    cudaGetSymbolAddress((void**)&binp, g_bin);

    const int GY = (NN + 127) / 128;   // 782

    // --- binning by dst ---
    cudaMemsetAsync(cntp, 0, NN * sizeof(int));
    cudaMemsetAsync(curp, 0, NN * sizeof(int));
    count_kernel<<<(NE + 255) / 256, 256>>>(dst, cntp);
    scan_kernel<<<1, 1024>>>(cntp, offp);
    scatter_kernel<<<(NE + 255) / 256, 256>>>(src, dst, offp, curp, binp);

    // --- fused QKV GEMM (tf32), Q fp32 + KV fp16 outputs ---
    packW_kernel<<<(D * D + 255) / 256, 256>>>(Wq, Wk, Wv, Wpkp);
    mma_gemm<0><<<dim3(3, GY), 256>>>(h, Wpkp, nullptr, nullptr, nullptr, nullptr,
                                      Qp, KVp, NN, 3 * D, D);

    // --- attention aggregation (atomic-free, fp16 gathers) ---
    {
        int blocks = (NN * 32 + 255) / 256;
        agg_kernel<<<blocks, 256>>>(offp, binp, Qp, KVp, wVp);
    }

    // hh = LN(h + head_out @ Wo + bo)
    mma_gemm<2><<<dim3(1, GY), 256>>>(wVp, Wo, bo, h, g1, b1,
                                      hhp, nullptr, NN, D, D);

    // t = relu(hh @ W1 + c1)
    mma_gemm<1><<<dim3(2, GY), 256>>>(hhp, W1, c1, nullptr, nullptr, nullptr,
                                      tp, nullptr, NN, 2 * D, D);

    // out = LN(hh + t @ W2 + c2)
    mma_gemm<2><<<dim3(1, GY), 256>>>(tp, W2, c2, hhp, g2, b2,
                                      out, nullptr, NN, D, 2 * D);
}